// round 2
// baseline (speedup 1.0000x reference)
#include <cuda_runtime.h>
#include <math.h>
#include <stdint.h>
#include <limits.h>

#define T_DIM   4096
#define V_DIM   4096
#define FW      5
#define B_DIM   64
#define S_DIM   512
#define NROWS   (B_DIM * S_DIM)      // 32768
#define NPAIRS  (T_DIM / 2)          // 2048
#define ROWBLKS (NROWS / 32)         // 1024
#define SLAB_ELEMS (V_DIM * FW)      // 20480 float2 entries

// Scratch logits: block layout [rowBlk][tpair][row-in-blk] as float2 (t=2c, 2c+1).
__device__ float2 g_scratch[(size_t)ROWBLKS * NPAIRS * 32];

// ---------------------------------------------------------------------------
__global__ void k0_zero(float* out) {
    if (threadIdx.x == 0) out[2 * NROWS] = 0.0f;
}

// ---------------------------------------------------------------------------
// K1: per t-pair CTA. Stage W[t0,:,:], W[t1,:,:] into SMEM interleaved float2,
// gather-sum for all 32768 rows in the reference's exact fp32 add order.
// ---------------------------------------------------------------------------
__global__ __launch_bounds__(512, 1)
void k1_logits(const float* __restrict__ W, const float* __restrict__ b,
               const int* __restrict__ x) {
    extern __shared__ float2 slab[];   // 20480 float2 = 160 KB

    const int c  = blockIdx.x;
    const int t0 = 2 * c;

    {
        const float4* w0 = (const float4*)(W + (size_t)t0 * SLAB_ELEMS);
        const float4* w1 = (const float4*)(W + (size_t)(t0 + 1) * SLAB_ELEMS);
        float4* slab4 = (float4*)slab;
        for (int i = threadIdx.x; i < SLAB_ELEMS / 4; i += 512) {
            float4 a = w0[i];
            float4 d = w1[i];
            slab4[2 * i + 0] = make_float4(a.x, d.x, a.y, d.y);
            slab4[2 * i + 1] = make_float4(a.z, d.z, a.w, d.w);
        }
    }
    const float2 bb = make_float2(b[t0], b[t0 + 1]);
    __syncthreads();

    const int s = threadIdx.x;
    const bool interior = (s >= 2) && (s <= S_DIM - 3);
    const int lane = threadIdx.x & 31;
    const int wsub = threadIdx.x >> 5;

    for (int bi = 0; bi < B_DIM; bi++) {
        const int* xr = x + bi * S_DIM;
        float2 a = bb;
        if (interior) {
            int v0 = xr[s - 2];
            int v1 = xr[s - 1];
            int v2 = xr[s];
            int v3 = xr[s + 1];
            int v4 = xr[s + 2];
            float2 w0 = slab[v0 * 5 + 0];
            float2 w1 = slab[v1 * 5 + 1];
            float2 w2 = slab[v2 * 5 + 2];
            float2 w3 = slab[v3 * 5 + 3];
            float2 w4 = slab[v4 * 5 + 4];
            a.x += w0.x; a.y += w0.y;
            a.x += w1.x; a.y += w1.y;
            a.x += w2.x; a.y += w2.y;
            a.x += w3.x; a.y += w3.y;
            a.x += w4.x; a.y += w4.y;
        } else {
            #pragma unroll
            for (int k = 0; k < FW; k++) {
                int j = s + k - 2;
                if (j >= 0 && j < S_DIM) {
                    float2 w = slab[xr[j] * 5 + k];
                    a.x += w.x; a.y += w.y;
                }
            }
        }
        size_t ridx = (((size_t)(bi * 16 + wsub)) * NPAIRS + c) * 32 + lane;
        g_scratch[ridx] = a;
    }
}

// ---------------------------------------------------------------------------
// K2: per row-block (32 rows) CTA of 1024 threads.
// warp = c-stripe, lane = row.  Pass 1: max + accurate sum(e^l) + sum(l e^l).
// Reduction -> m, lse_f, entropy.  Pass 2: tie-aware argmax replicating
// jnp.argmax(exp(log_softmax(l))) first-index tie semantics via the rounded
// key RN(RN(l-m) - lse_f).
// ---------------------------------------------------------------------------
__global__ __launch_bounds__(1024)
void k2_softmax(float* __restrict__ out) {
    __shared__ float  sm_m[32][33];
    __shared__ double sm_s[32][33];
    __shared__ float  sm_w[32][33];
    __shared__ float  row_m[32];
    __shared__ float  row_lse[32];
    __shared__ int    row_cand[32];

    const int rblk = blockIdx.x;
    const int warp = threadIdx.x >> 5;
    const int lane = threadIdx.x & 31;

    const float2* base = g_scratch + (size_t)rblk * NPAIRS * 32;

    // ---- pass 1 ----
    float  m  = -INFINITY;
    double sd = 0.0;
    float  w  = 0.0f;

    #pragma unroll 4
    for (int i = 0; i < NPAIRS / 32; i++) {
        int c = i * 32 + warp;
        float2 v = base[(size_t)c * 32 + lane];
        m = fmaxf(m, fmaxf(v.x, v.y));
        float e1 = __expf(v.x);
        float e2 = __expf(v.y);
        sd += (double)(e1 + e2);
        w = fmaf(v.x, e1, w);
        w = fmaf(v.y, e2, w);
    }

    sm_m[warp][lane] = m;
    sm_s[warp][lane] = sd;
    sm_w[warp][lane] = w;
    __syncthreads();

    // ---- reduction: warp `warp` reduces row `warp` ----
    {
        float  m2 = sm_m[lane][warp];
        double s2 = sm_s[lane][warp];
        float  w2 = sm_w[lane][warp];
        #pragma unroll
        for (int off = 16; off > 0; off >>= 1) {
            m2 = fmaxf(m2, __shfl_down_sync(0xffffffffu, m2, off));
            s2 += __shfl_down_sync(0xffffffffu, s2, off);
            w2 += __shfl_down_sync(0xffffffffu, w2, off);
        }
        if (lane == 0) {
            double ls0 = log(s2);                       // ln(sum e^l), double
            float  lse_f = (float)(ls0 - (double)m2);   // ref's log(sum e^{l-m})
            row_m[warp]   = m2;
            row_lse[warp] = lse_f;
            row_cand[warp] = INT_MAX;
            int r = rblk * 32 + warp;
            out[NROWS + r] = -lse_f;                    // log_p at argmax (tie key)
            float H = (float)ls0 - (float)(s2 != 0.0 ? (double)w2 / s2 : 0.0);
            atomicAdd(out + 2 * NROWS,
                      H * (1.0f / ((float)NROWS * (float)T_DIM)));
        }
    }
    __syncthreads();

    // ---- pass 2: tie-aware argmax (rare rescan) ----
    {
        float m2   = row_m[lane];
        float lsef = row_lse[lane];
        float nlse = 0.0f - lsef;          // key of the max element
        if (m >= m2 - 2e-6f) {             // this stripe may hold a candidate
            for (int i = 0; i < NPAIRS / 32; i++) {
                int c = i * 32 + warp;
                float2 v = base[(size_t)c * 32 + lane];
                float shx = v.x - m2;
                if (shx > -2e-6f) {
                    float kx = shx - lsef;
                    if (kx == nlse) atomicMin(&row_cand[lane], 2 * c);
                }
                float shy = v.y - m2;
                if (shy > -2e-6f) {
                    float ky = shy - lsef;
                    if (ky == nlse) atomicMin(&row_cand[lane], 2 * c + 1);
                }
            }
        }
    }
    __syncthreads();

    if (warp == 0) {
        out[rblk * 32 + lane] = (float)row_cand[lane];
    }
}

// ---------------------------------------------------------------------------
extern "C" void kernel_launch(void* const* d_in, const int* in_sizes, int n_in,
                              void* d_out, int out_size) {
    const float* W = nullptr;
    const float* b = nullptr;
    const int*   x = nullptr;
    for (int i = 0; i < n_in; i++) {
        if (in_sizes[i] == T_DIM * V_DIM * FW) W = (const float*)d_in[i];
        else if (in_sizes[i] == T_DIM)         b = (const float*)d_in[i];
        else if (in_sizes[i] == NROWS)         x = (const int*)d_in[i];
    }
    float* out = (float*)d_out;

    cudaFuncSetAttribute(k1_logits, cudaFuncAttributeMaxDynamicSharedMemorySize,
                         SLAB_ELEMS * (int)sizeof(float2));

    k0_zero<<<1, 32>>>(out);
    k1_logits<<<NPAIRS, 512, SLAB_ELEMS * sizeof(float2)>>>(W, b, x);
    k2_softmax<<<ROWBLKS, 1024>>>(out);
}